// round 16
// baseline (speedup 1.0000x reference)
#include <cuda_runtime.h>
#include <cuda_fp16.h>
#include <math.h>
#include <stdint.h>

// Problem dims
constexpr int ROWS = 8 * 1024;   // N*S = 8192
constexpr int E    = 768;
constexpr int E3   = 2304;
constexpr int FF   = 3072;

// ---------------------------------------------------------------------------
// Scratch (device globals: allocation-guard safe)
// ---------------------------------------------------------------------------
__device__ float g_x1[(size_t)ROWS * E];
__device__ __half g_h[(size_t)ROWS * E];
__device__ __half g_attn[(size_t)ROWS * E];
__device__ __half g_ff[(size_t)ROWS * FF];
// Per-head QKV: [n(8)][h(12)][s(1024)][d(64)] fp16; Q pre-scaled by 0.125*log2(e)
__device__ __half g_q[(size_t)ROWS * E];
__device__ __half g_k[(size_t)ROWS * E];
__device__ __half g_v[(size_t)ROWS * E];
// Transposed fp16 weights: [N, K]
__device__ __half g_wqkv[(size_t)E3 * E];
__device__ __half g_wproj[(size_t)E * E];
__device__ __half g_wfc[(size_t)FF * E];
__device__ __half g_wfc2[(size_t)E * FF];

// ---------------------------------------------------------------------------
// Helpers (baseline compute_103 PTX: cp.async + mma.sync + ldmatrix)
// ---------------------------------------------------------------------------
__device__ __forceinline__ uint32_t smem_u32(const void* p) {
    uint32_t a;
    asm("{ .reg .u64 t; cvta.to.shared.u64 t, %1; cvt.u32.u64 %0, t; }" : "=r"(a) : "l"(p));
    return a;
}

#define CP_ASYNC16(dst, src) asm volatile("cp.async.cg.shared.global [%0], [%1], 16;" :: "r"(dst), "l"(src))
#define CP_COMMIT()          asm volatile("cp.async.commit_group;" ::: "memory")
#define CP_WAIT(n)           asm volatile("cp.async.wait_group %0;" :: "n"(n) : "memory")

#define MMA16816F16(d, a0, a1, a2, a3, b0, b1) \
    asm volatile( \
        "mma.sync.aligned.m16n8k16.row.col.f32.f16.f16.f32 " \
        "{%0,%1,%2,%3}, {%4,%5,%6,%7}, {%8,%9}, {%0,%1,%2,%3};" \
        : "+f"((d)[0]), "+f"((d)[1]), "+f"((d)[2]), "+f"((d)[3]) \
        : "r"(a0), "r"(a1), "r"(a2), "r"(a3), "r"(b0), "r"(b1))

#define LDMX4(r0, r1, r2, r3, addr) \
    asm volatile("ldmatrix.sync.aligned.m8n8.x4.shared.b16 {%0,%1,%2,%3}, [%4];" \
        : "=r"(r0), "=r"(r1), "=r"(r2), "=r"(r3) : "r"(addr))

#define LDMX4T(r0, r1, r2, r3, addr) \
    asm volatile("ldmatrix.sync.aligned.m8n8.x4.trans.shared.b16 {%0,%1,%2,%3}, [%4];" \
        : "=r"(r0), "=r"(r1), "=r"(r2), "=r"(r3) : "r"(addr))

__device__ __forceinline__ uint32_t packh2(float a, float b) {
    __half2 h = __floats2half2_rn(a, b);
    return *(uint32_t*)&h;
}

// ---------------------------------------------------------------------------
// LayerNorm body: one WARP per row, register-resident, shfl-only reduce.
// ---------------------------------------------------------------------------
__device__ __forceinline__ void ln_body(int row, int lane,
                                        const float* __restrict__ x,
                                        const float* __restrict__ g,
                                        const float* __restrict__ b,
                                        __half* __restrict__ out) {
    const float4* xr = (const float4*)(x + (size_t)row * E);

    float4 v[6];
    float s = 0.f;
    #pragma unroll
    for (int i = 0; i < 6; i++) {
        v[i] = xr[lane + 32 * i];
        s += (v[i].x + v[i].y) + (v[i].z + v[i].w);
    }
    #pragma unroll
    for (int o = 16; o > 0; o >>= 1) s += __shfl_xor_sync(0xffffffffu, s, o);
    float mu = s * (1.0f / E);

    float sq = 0.f;
    #pragma unroll
    for (int i = 0; i < 6; i++) {
        v[i].x -= mu; v[i].y -= mu; v[i].z -= mu; v[i].w -= mu;
        sq += v[i].x * v[i].x + v[i].y * v[i].y + v[i].z * v[i].z + v[i].w * v[i].w;
    }
    #pragma unroll
    for (int o = 16; o > 0; o >>= 1) sq += __shfl_xor_sync(0xffffffffu, sq, o);
    float rs = rsqrtf(sq * (1.0f / E) + 1e-5f);

    const float4* gv = (const float4*)g;
    const float4* bv = (const float4*)b;
    uint2* orow = (uint2*)(out + (size_t)row * E);
    #pragma unroll
    for (int i = 0; i < 6; i++) {
        int j = lane + 32 * i;
        float4 gg = gv[j], bb = bv[j];
        float o0 = v[i].x * rs * gg.x + bb.x;
        float o1 = v[i].y * rs * gg.y + bb.y;
        float o2 = v[i].z * rs * gg.z + bb.z;
        float o3 = v[i].w * rs * gg.w + bb.w;
        uint2 pk;
        pk.x = packh2(o0, o1);
        pk.y = packh2(o2, o3);
        orow[j] = pk;
    }
}

__global__ void __launch_bounds__(256) ln_kernel(const float* __restrict__ x,
                                                 const float* __restrict__ g,
                                                 const float* __restrict__ b,
                                                 __half* __restrict__ out) {
    ln_body(blockIdx.x * 8 + (threadIdx.x >> 5), threadIdx.x & 31, x, g, b, out);
}

// ---------------------------------------------------------------------------
// Weight transpose body: w[K,N] fp32 tile -> o[N,K] fp16.
// ---------------------------------------------------------------------------
__device__ __forceinline__ void wsplit_body(int blk,
    const float* __restrict__ w0, const float* __restrict__ w1,
    const float* __restrict__ w2, const float* __restrict__ w3,
    __half* __restrict__ o0, __half* __restrict__ o1,
    __half* __restrict__ o2, __half* __restrict__ o3) {
    __shared__ float t[32][33];
    const float* w; __half* o; int K, N, bx, by;
    if (blk < 1728)      { blk -= 0;    w = w0; o = o0; K = 768;  N = 2304; bx = blk % 72; by = blk / 72; }
    else if (blk < 2304) { blk -= 1728; w = w1; o = o1; K = 768;  N = 768;  bx = blk % 24; by = blk / 24; }
    else if (blk < 4608) { blk -= 2304; w = w2; o = o2; K = 768;  N = 3072; bx = blk % 96; by = blk / 96; }
    else                 { blk -= 4608; w = w3; o = o3; K = 3072; N = 768;  bx = blk % 24; by = blk / 24; }
    int n0 = bx * 32, k0 = by * 32;
    int tx = threadIdx.x & 31, ty = threadIdx.x >> 5;
    #pragma unroll
    for (int j = 0; j < 32; j += 8)
        t[ty + j][tx] = w[(size_t)(k0 + ty + j) * N + n0 + tx];
    __syncthreads();
    #pragma unroll
    for (int j = 0; j < 32; j += 8)
        o[(size_t)(n0 + ty + j) * K + k0 + tx] = __float2half_rn(t[tx][ty + j]);
}

// Fused prelude: blocks [0,6912) transpose weights; [6912,7936) do LN1.
__global__ void __launch_bounds__(256) prelude_kernel(
    const float* __restrict__ w0, const float* __restrict__ w1,
    const float* __restrict__ w2, const float* __restrict__ w3,
    __half* __restrict__ o0, __half* __restrict__ o1,
    __half* __restrict__ o2, __half* __restrict__ o3,
    const float* __restrict__ x, const float* __restrict__ ln_g,
    const float* __restrict__ ln_b, __half* __restrict__ h) {
    int blk = blockIdx.x;
    if (blk < 6912) {
        wsplit_body(blk, w0, w1, w2, w3, o0, o1, o2, o3);
    } else {
        ln_body((blk - 6912) * 8 + (threadIdx.x >> 5), threadIdx.x & 31, x, ln_g, ln_b, h);
    }
}

// ---------------------------------------------------------------------------
// fp16 mma.sync GEMM (R14-frozen): C[M,N] = A[M,K] @ B[N,K]^T + bias
// CTA 128x128, BK=64, 8 warps (4 M x 2 N), warp tile 32x64.
// 3-stage cp.async pipeline, rows padded to 144B (conflict-free ldmatrix).
// MODE 1: fp32 +bias+residual;  MODE 2: +bias, GELU -> fp16
// MODE 3: fp16 qkv scatter to per-head q/k/v (q scaled by 0.125*log2e)
// ---------------------------------------------------------------------------
constexpr int GBK = 64;
constexpr int RSTRIDE = 144;                    // 128B payload + 16B pad
constexpr int STAGE_B = 256 * RSTRIDE;          // A(128 rows) + B(128 rows): 36864 B
constexpr int NSTAGE = 3;
constexpr size_t GEMM_SMEM = (size_t)NSTAGE * STAGE_B;  // 110592 B

template <int MODE>
__global__ void __launch_bounds__(256, 2) gemm_mma(
    const __half* __restrict__ A, const __half* __restrict__ B,
    const float* __restrict__ bias, const float* __restrict__ res,
    float* __restrict__ C, __half* __restrict__ Ch,
    __half* __restrict__ Qo, __half* __restrict__ Ko, __half* __restrict__ Vo,
    int Ndim, int Kdim) {
    extern __shared__ __align__(16) char smem[];
    uint32_t sb = smem_u32(smem);
    int tid = threadIdx.x, wid = tid >> 5, lane = tid & 31;
    int wm = wid & 3, wn = wid >> 2;           // warp grid 4 (M) x 2 (N)
    int m0 = blockIdx.y * 128, n0 = blockIdx.x * 128;
    int r = lane >> 2, c2 = (lane & 3) * 2;
    int lrow = lane & 15, lcol = (lane >> 4) * 16;

    float acc[2][8][4];
    #pragma unroll
    for (int mi = 0; mi < 2; mi++)
        #pragma unroll
        for (int ni = 0; ni < 8; ni++)
            #pragma unroll
            for (int q = 0; q < 4; q++) acc[mi][ni][q] = 0.f;

    // 2048 16B chunks per stage (256 rows x 8 chunks), 8 per thread
    auto load_stage = [&](int it, int buf) {
        int k0 = it * GBK;
        #pragma unroll
        for (int i = 0; i < 8; i++) {
            int ch = i * 256 + tid;
            int row = ch >> 3, kc = ch & 7;
            uint32_t dst = sb + buf * STAGE_B + row * RSTRIDE + kc * 16;
            const __half* src = (row < 128 ? A + (size_t)(m0 + row) * Kdim
                                           : B + (size_t)(n0 + row - 128) * Kdim)
                                + k0 + kc * 8;
            CP_ASYNC16(dst, src);
        }
        CP_COMMIT();
    };

    load_stage(0, 0);
    load_stage(1, 1);

    int niter = Kdim / GBK;
    for (int it = 0; it < niter; ++it) {
        int buf = it % NSTAGE;
        if (it + 1 < niter) CP_WAIT(1); else CP_WAIT(0);
        __syncthreads();
        if (it + 2 < niter) load_stage(it + 2, (it + 2) % NSTAGE);

        uint32_t abase = sb + buf * STAGE_B;
        uint32_t bbase = abase + 128 * RSTRIDE;

        #pragma unroll
        for (int ks = 0; ks < 4; ks++) {
            uint32_t ah[2][4];
            #pragma unroll
            for (int mi = 0; mi < 2; mi++) {
                uint32_t addr = abase + (wm * 32 + mi * 16 + lrow) * RSTRIDE + ks * 32 + lcol;
                LDMX4(ah[mi][0], ah[mi][1], ah[mi][2], ah[mi][3], addr);
            }
            #pragma unroll
            for (int nb = 0; nb < 4; nb++) {
                uint32_t b0, b1, b2, b3;
                uint32_t addr = bbase + (wn * 64 + nb * 16 + lrow) * RSTRIDE + ks * 32 + lcol;
                LDMX4(b0, b1, b2, b3, addr);
                #pragma unroll
                for (int mi = 0; mi < 2; mi++) {
                    MMA16816F16(acc[mi][2 * nb],     ah[mi][0], ah[mi][1], ah[mi][2], ah[mi][3], b0, b2);
                    MMA16816F16(acc[mi][2 * nb + 1], ah[mi][0], ah[mi][1], ah[mi][2], ah[mi][3], b1, b3);
                }
            }
        }
    }

    // Epilogue: direct register writeout
    #pragma unroll
    for (int mi = 0; mi < 2; mi++) {
        #pragma unroll
        for (int ni = 0; ni < 8; ni++) {
            int row = m0 + wm * 32 + mi * 16 + r;
            int col = n0 + wn * 64 + ni * 8 + c2;
            float2 bv = *(const float2*)&bias[col];
            #pragma unroll
            for (int hf = 0; hf < 2; hf++) {
                int rr = row + hf * 8;
                float v0 = acc[mi][ni][hf * 2 + 0] + bv.x;
                float v1 = acc[mi][ni][hf * 2 + 1] + bv.y;
                if (MODE == 3) {
                    int which = col / 768;
                    int h = (col % 768) >> 6;
                    int d = col & 63;
                    size_t dst = ((size_t)((rr >> 10) * 12 + h) * 1024 + (rr & 1023)) * 64 + d;
                    __half* base = (which == 0) ? Qo : (which == 1) ? Ko : Vo;
                    float sc = (which == 0) ? 0.1803368823f : 1.0f;  // 0.125*log2(e)
                    *(__half2*)&base[dst] = __floats2half2_rn(v0 * sc, v1 * sc);
                } else {
                    size_t gi = (size_t)rr * Ndim + col;
                    if (MODE == 2) {
                        v0 = 0.5f * v0 * (1.0f + erff(v0 * 0.70710678118f));
                        v1 = 0.5f * v1 * (1.0f + erff(v1 * 0.70710678118f));
                        *(__half2*)&Ch[gi] = __floats2half2_rn(v0, v1);
                    } else {
                        float2 rv = *(const float2*)&res[gi];
                        v0 += rv.x; v1 += rv.y;
                        *(float2*)&C[gi] = make_float2(v0, v1);
                    }
                }
            }
        }
    }
}

// ---------------------------------------------------------------------------
// Tensor-core flash attention (fp16 mma, FA2-style), 64-row Q tiles,
// 128 threads, 3-slot KV ring with 2-deep cp.async prefetch.
// Q is staged through K-slot 2 (consumed into registers before tile-2
// prefetch overwrites it; barrier-protected) so SMEM stays 6 tiles.
// qt mapped DESCENDING so long CTAs schedule first.
// ---------------------------------------------------------------------------
constexpr int AQS = 72;                         // padded row stride (halves) = 144B
constexpr int ATT_TILE_B = 64 * AQS * 2;        // 9216 B
constexpr size_t ATT_SMEM = 6 * ATT_TILE_B;     // 3*K + 3*V = 55296 B

__global__ void __launch_bounds__(128) attn_kernel() {
    extern __shared__ __align__(16) char smem[];
    uint32_t sb = smem_u32(smem);
    uint32_t Kb[3] = {sb, sb + ATT_TILE_B, sb + 2 * ATT_TILE_B};
    uint32_t Vb[3] = {sb + 3 * ATT_TILE_B, sb + 4 * ATT_TILE_B, sb + 5 * ATT_TILE_B};
    uint32_t Qb = Kb[2];                        // Q staged in K slot 2

    int qt = (int)(gridDim.x - 1 - blockIdx.x);  // long CTAs first
    int nh = blockIdx.y;                        // n*12 + h
    size_t hbase = (size_t)nh * 1024 * 64;      // head base in g_q/g_k/g_v
    int n = nh / 12, h = nh % 12;
    int tid = threadIdx.x, wid = tid >> 5, lane = tid & 31;
    int r = lane >> 2, c2 = (lane & 3) * 2;
    int lrow = lane & 15, lcol = (lane >> 4) * 16;  // 16B units

    // tile loader: 64 rows x 128B, 512 chunks, 4/thread (no commit)
    auto load_tile = [&](const __half* g, int t0, uint32_t dstb) {
        #pragma unroll
        for (int i = 0; i < 4; i++) {
            int ch = i * 128 + tid;
            int row = ch >> 3, kc = ch & 7;
            CP_ASYNC16(dstb + row * (AQS * 2) + kc * 16,
                       g + hbase + (size_t)(t0 + row) * 64 + kc * 8);
        }
    };

    // Preload: group0 = {Q, K0, V0}; group1 = {K1, V1} (if any)
    load_tile(g_q, qt * 64, Qb);
    load_tile(g_k, 0, Kb[0]);
    load_tile(g_v, 0, Vb[0]);
    CP_COMMIT();
    if (qt > 0) {
        load_tile(g_k, 64, Kb[1]);
        load_tile(g_v, 64, Vb[1]);
        CP_COMMIT();
    }
    CP_WAIT(0);
    __syncthreads();

    // Q fragments live in registers for the whole kernel: 4 k16-blocks
    uint32_t qf[4][4];
    #pragma unroll
    for (int kb = 0; kb < 4; kb++) {
        uint32_t addr = Qb + (wid * 16 + lrow) * (AQS * 2) + kb * 32 + lcol;
        LDMX4(qf[kb][0], qf[kb][1], qf[kb][2], qf[kb][3], addr);
    }
    __syncthreads();   // qf consumed before tile-2 prefetch may overwrite Qb

    float m0v = -1e30f, m1v = -1e30f, l0 = 0.f, l1 = 0.f;
    float o[8][4];
    #pragma unroll
    for (int db = 0; db < 8; db++)
        #pragma unroll
        for (int q = 0; q < 4; q++) o[db][q] = 0.f;

    for (int t = 0; t <= qt; ++t) {
        int buf = t % 3;
        if (t + 2 <= qt) {
            load_tile(g_k, (t + 2) * 64, Kb[(t + 2) % 3]);
            load_tile(g_v, (t + 2) * 64, Vb[(t + 2) % 3]);
            CP_COMMIT();
        }

        // S = Q @ K^T  (16 x 64 per warp)  — values in log2 domain
        float s[8][4];
        #pragma unroll
        for (int nb = 0; nb < 8; nb++)
            #pragma unroll
            for (int q = 0; q < 4; q++) s[nb][q] = 0.f;
        #pragma unroll
        for (int kb = 0; kb < 4; kb++) {
            #pragma unroll
            for (int nb16 = 0; nb16 < 4; nb16++) {
                uint32_t b0, b1, b2, b3;
                uint32_t addr = Kb[buf] + (nb16 * 16 + lrow) * (AQS * 2) + kb * 32 + lcol;
                LDMX4(b0, b1, b2, b3, addr);
                MMA16816F16(s[nb16 * 2],     qf[kb][0], qf[kb][1], qf[kb][2], qf[kb][3], b0, b2);
                MMA16816F16(s[nb16 * 2 + 1], qf[kb][0], qf[kb][1], qf[kb][2], qf[kb][3], b1, b3);
            }
        }

        // Causal mask on diagonal tile
        if (t == qt) {
            int row0 = qt * 64 + wid * 16 + r;
            #pragma unroll
            for (int nb = 0; nb < 8; nb++) {
                int col = t * 64 + nb * 8 + c2;
                if (col > row0)     s[nb][0] = -1e30f;
                if (col + 1 > row0) s[nb][1] = -1e30f;
                if (col > row0 + 8)     s[nb][2] = -1e30f;
                if (col + 1 > row0 + 8) s[nb][3] = -1e30f;
            }
        }

        // Online softmax (rows r and r+8 of this warp's 16), exp2 domain
        float mx0 = -1e30f, mx1 = -1e30f;
        #pragma unroll
        for (int nb = 0; nb < 8; nb++) {
            mx0 = fmaxf(mx0, fmaxf(s[nb][0], s[nb][1]));
            mx1 = fmaxf(mx1, fmaxf(s[nb][2], s[nb][3]));
        }
        mx0 = fmaxf(mx0, __shfl_xor_sync(0xffffffffu, mx0, 1));
        mx0 = fmaxf(mx0, __shfl_xor_sync(0xffffffffu, mx0, 2));
        mx1 = fmaxf(mx1, __shfl_xor_sync(0xffffffffu, mx1, 1));
        mx1 = fmaxf(mx1, __shfl_xor_sync(0xffffffffu, mx1, 2));

        float nm0 = fmaxf(m0v, mx0), nm1 = fmaxf(m1v, mx1);
        float f0 = exp2f(m0v - nm0), f1 = exp2f(m1v - nm1);
        float ls0 = 0.f, ls1 = 0.f;
        #pragma unroll
        for (int nb = 0; nb < 8; nb++) {
            s[nb][0] = exp2f(s[nb][0] - nm0); ls0 += s[nb][0];
            s[nb][1] = exp2f(s[nb][1] - nm0); ls0 += s[nb][1];
            s[nb][2] = exp2f(s[nb][2] - nm1); ls1 += s[nb][2];
            s[nb][3] = exp2f(s[nb][3] - nm1); ls1 += s[nb][3];
        }
        l0 = l0 * f0 + ls0;
        l1 = l1 * f1 + ls1;
        m0v = nm0; m1v = nm1;
        #pragma unroll
        for (int db = 0; db < 8; db++) {
            o[db][0] *= f0; o[db][1] *= f0;
            o[db][2] *= f1; o[db][3] *= f1;
        }

        // O += P @ V  (P fp16 from registers)
        #pragma unroll
        for (int kb2 = 0; kb2 < 4; kb2++) {
            uint32_t a0 = packh2(s[2 * kb2][0],     s[2 * kb2][1]);
            uint32_t a1 = packh2(s[2 * kb2][2],     s[2 * kb2][3]);
            uint32_t a2 = packh2(s[2 * kb2 + 1][0], s[2 * kb2 + 1][1]);
            uint32_t a3 = packh2(s[2 * kb2 + 1][2], s[2 * kb2 + 1][3]);
            #pragma unroll
            for (int db2 = 0; db2 < 4; db2++) {
                uint32_t v0, v1, v2, v3;
                uint32_t addr = Vb[buf] + (kb2 * 16 + lrow) * (AQS * 2) + db2 * 32 + lcol;
                LDMX4T(v0, v1, v2, v3, addr);
                MMA16816F16(o[db2 * 2],     a0, a1, a2, a3, v0, v1);
                MMA16816F16(o[db2 * 2 + 1], a0, a1, a2, a3, v2, v3);
            }
        }

        if (t < qt) {
            if (t + 2 <= qt) CP_WAIT(1); else CP_WAIT(0);
            __syncthreads();
        }
    }

    l0 += __shfl_xor_sync(0xffffffffu, l0, 1);
    l0 += __shfl_xor_sync(0xffffffffu, l0, 2);
    l1 += __shfl_xor_sync(0xffffffffu, l1, 1);
    l1 += __shfl_xor_sync(0xffffffffu, l1, 2);
    float inv0 = 1.f / l0, inv1 = 1.f / l1;

    int row0 = n * 1024 + qt * 64 + wid * 16 + r;
    int colb = h * 64;
    #pragma unroll
    for (int db = 0; db < 8; db++) {
        size_t gi0 = (size_t)row0 * 768 + colb + db * 8 + c2;
        size_t gi1 = (size_t)(row0 + 8) * 768 + colb + db * 8 + c2;
        *(__half2*)&g_attn[gi0] = __floats2half2_rn(o[db][0] * inv0, o[db][1] * inv0);
        *(__half2*)&g_attn[gi1] = __floats2half2_rn(o[db][2] * inv1, o[db][3] * inv1);
    }
}

// ---------------------------------------------------------------------------
extern "C" void kernel_launch(void* const* d_in, const int* in_sizes, int n_in,
                              void* d_out, int out_size) {
    const float* x      = (const float*)d_in[0];
    const float* ln1_g  = (const float*)d_in[1];
    const float* ln1_b  = (const float*)d_in[2];
    const float* ln2_g  = (const float*)d_in[3];
    const float* ln2_b  = (const float*)d_in[4];
    const float* w_attn = (const float*)d_in[5];
    const float* b_attn = (const float*)d_in[6];
    const float* w_proj = (const float*)d_in[7];
    const float* b_proj = (const float*)d_in[8];
    const float* w_fc   = (const float*)d_in[9];
    const float* b_fc   = (const float*)d_in[10];
    const float* w_fc2  = (const float*)d_in[11];
    const float* b_fc2  = (const float*)d_in[12];
    float* out = (float*)d_out;

    float* p_x1;
    __half *p_h, *p_attn, *p_ff, *p_q, *p_k, *p_v;
    __half *p_wq, *p_wp, *p_wf, *p_w2;
    cudaGetSymbolAddress((void**)&p_x1, g_x1);
    cudaGetSymbolAddress((void**)&p_h, g_h);
    cudaGetSymbolAddress((void**)&p_attn, g_attn);
    cudaGetSymbolAddress((void**)&p_ff, g_ff);
    cudaGetSymbolAddress((void**)&p_q, g_q);
    cudaGetSymbolAddress((void**)&p_k, g_k);
    cudaGetSymbolAddress((void**)&p_v, g_v);
    cudaGetSymbolAddress((void**)&p_wq, g_wqkv);
    cudaGetSymbolAddress((void**)&p_wp, g_wproj);
    cudaGetSymbolAddress((void**)&p_wf, g_wfc);
    cudaGetSymbolAddress((void**)&p_w2, g_wfc2);

    cudaFuncSetAttribute(gemm_mma<1>, cudaFuncAttributeMaxDynamicSharedMemorySize, (int)GEMM_SMEM);
    cudaFuncSetAttribute(gemm_mma<2>, cudaFuncAttributeMaxDynamicSharedMemorySize, (int)GEMM_SMEM);
    cudaFuncSetAttribute(gemm_mma<3>, cudaFuncAttributeMaxDynamicSharedMemorySize, (int)GEMM_SMEM);
    cudaFuncSetAttribute(attn_kernel, cudaFuncAttributeMaxDynamicSharedMemorySize, (int)ATT_SMEM);

    // 0+1. fused prelude: weight transposes + LN1
    prelude_kernel<<<7936, 256>>>(w_attn, w_proj, w_fc, w_fc2,
                                  p_wq, p_wp, p_wf, p_w2,
                                  x, ln1_g, ln1_b, p_h);
    // 2. qkv GEMM -> per-head q/k/v fp16 (q scaled by 0.125*log2e)
    gemm_mma<3><<<dim3(18, 64), 256, GEMM_SMEM>>>(p_h, p_wq, b_attn, nullptr,
        nullptr, nullptr, p_q, p_k, p_v, E3, E);
    // 3. tensor-core causal flash attention -> attn (fp16 [rows, E])
    attn_kernel<<<dim3(16, 96), 128, ATT_SMEM>>>();
    // 4. x1 = x + attn @ w_proj + b_proj
    gemm_mma<1><<<dim3(6, 64), 256, GEMM_SMEM>>>(p_attn, p_wp, b_proj, x,
        p_x1, nullptr, nullptr, nullptr, nullptr, E, E);
    // 5. LN2 -> h (fp16)
    ln_kernel<<<1024, 256>>>(p_x1, ln2_g, ln2_b, p_h);
    // 6. ff = gelu(h @ w_fc + b_fc) -> fp16
    gemm_mma<2><<<dim3(24, 64), 256, GEMM_SMEM>>>(p_h, p_wf, b_fc, nullptr,
        nullptr, p_ff, nullptr, nullptr, nullptr, FF, E);
    // 7. out = x1 + ff @ w_fc2 + b_fc2
    gemm_mma<1><<<dim3(6, 64), 256, GEMM_SMEM>>>(p_ff, p_w2, b_fc2, p_x1,
        out, nullptr, nullptr, nullptr, nullptr, E, FF);
}

// round 17
// speedup vs baseline: 1.5339x; 1.5339x over previous
#include <cuda_runtime.h>
#include <cuda_fp16.h>
#include <math.h>
#include <stdint.h>

// Problem dims
constexpr int ROWS = 8 * 1024;   // N*S = 8192
constexpr int E    = 768;
constexpr int E3   = 2304;
constexpr int FF   = 3072;

// ---------------------------------------------------------------------------
// Scratch (device globals: allocation-guard safe)
// ---------------------------------------------------------------------------
__device__ float g_x1[(size_t)ROWS * E];
__device__ __half g_h[(size_t)ROWS * E];
__device__ __half g_attn[(size_t)ROWS * E];
__device__ __half g_ff[(size_t)ROWS * FF];
// Per-head QKV: [n(8)][h(12)][s(1024)][d(64)] fp16; Q pre-scaled by 0.125*log2(e)
__device__ __half g_q[(size_t)ROWS * E];
__device__ __half g_k[(size_t)ROWS * E];
__device__ __half g_v[(size_t)ROWS * E];
// Transposed fp16 weights: [N, K]
__device__ __half g_wqkv[(size_t)E3 * E];
__device__ __half g_wproj[(size_t)E * E];
__device__ __half g_wfc[(size_t)FF * E];
__device__ __half g_wfc2[(size_t)E * FF];

// ---------------------------------------------------------------------------
// Helpers (baseline compute_103 PTX: cp.async + mma.sync + ldmatrix)
// ---------------------------------------------------------------------------
__device__ __forceinline__ uint32_t smem_u32(const void* p) {
    uint32_t a;
    asm("{ .reg .u64 t; cvta.to.shared.u64 t, %1; cvt.u32.u64 %0, t; }" : "=r"(a) : "l"(p));
    return a;
}

#define CP_ASYNC16(dst, src) asm volatile("cp.async.cg.shared.global [%0], [%1], 16;" :: "r"(dst), "l"(src))
#define CP_COMMIT()          asm volatile("cp.async.commit_group;" ::: "memory")
#define CP_WAIT(n)           asm volatile("cp.async.wait_group %0;" :: "n"(n) : "memory")

#define MMA16816F16(d, a0, a1, a2, a3, b0, b1) \
    asm volatile( \
        "mma.sync.aligned.m16n8k16.row.col.f32.f16.f16.f32 " \
        "{%0,%1,%2,%3}, {%4,%5,%6,%7}, {%8,%9}, {%0,%1,%2,%3};" \
        : "+f"((d)[0]), "+f"((d)[1]), "+f"((d)[2]), "+f"((d)[3]) \
        : "r"(a0), "r"(a1), "r"(a2), "r"(a3), "r"(b0), "r"(b1))

#define LDMX4(r0, r1, r2, r3, addr) \
    asm volatile("ldmatrix.sync.aligned.m8n8.x4.shared.b16 {%0,%1,%2,%3}, [%4];" \
        : "=r"(r0), "=r"(r1), "=r"(r2), "=r"(r3) : "r"(addr))

#define LDMX4T(r0, r1, r2, r3, addr) \
    asm volatile("ldmatrix.sync.aligned.m8n8.x4.trans.shared.b16 {%0,%1,%2,%3}, [%4];" \
        : "=r"(r0), "=r"(r1), "=r"(r2), "=r"(r3) : "r"(addr))

__device__ __forceinline__ uint32_t packh2(float a, float b) {
    __half2 h = __floats2half2_rn(a, b);
    return *(uint32_t*)&h;
}

// ---------------------------------------------------------------------------
// LayerNorm body: one WARP per row, register-resident, shfl-only reduce.
// ---------------------------------------------------------------------------
__device__ __forceinline__ void ln_body(int row, int lane,
                                        const float* __restrict__ x,
                                        const float* __restrict__ g,
                                        const float* __restrict__ b,
                                        __half* __restrict__ out) {
    const float4* xr = (const float4*)(x + (size_t)row * E);

    float4 v[6];
    float s = 0.f;
    #pragma unroll
    for (int i = 0; i < 6; i++) {
        v[i] = xr[lane + 32 * i];
        s += (v[i].x + v[i].y) + (v[i].z + v[i].w);
    }
    #pragma unroll
    for (int o = 16; o > 0; o >>= 1) s += __shfl_xor_sync(0xffffffffu, s, o);
    float mu = s * (1.0f / E);

    float sq = 0.f;
    #pragma unroll
    for (int i = 0; i < 6; i++) {
        v[i].x -= mu; v[i].y -= mu; v[i].z -= mu; v[i].w -= mu;
        sq += v[i].x * v[i].x + v[i].y * v[i].y + v[i].z * v[i].z + v[i].w * v[i].w;
    }
    #pragma unroll
    for (int o = 16; o > 0; o >>= 1) sq += __shfl_xor_sync(0xffffffffu, sq, o);
    float rs = rsqrtf(sq * (1.0f / E) + 1e-5f);

    const float4* gv = (const float4*)g;
    const float4* bv = (const float4*)b;
    uint2* orow = (uint2*)(out + (size_t)row * E);
    #pragma unroll
    for (int i = 0; i < 6; i++) {
        int j = lane + 32 * i;
        float4 gg = gv[j], bb = bv[j];
        float o0 = v[i].x * rs * gg.x + bb.x;
        float o1 = v[i].y * rs * gg.y + bb.y;
        float o2 = v[i].z * rs * gg.z + bb.z;
        float o3 = v[i].w * rs * gg.w + bb.w;
        uint2 pk;
        pk.x = packh2(o0, o1);
        pk.y = packh2(o2, o3);
        orow[j] = pk;
    }
}

__global__ void __launch_bounds__(256) ln_kernel(const float* __restrict__ x,
                                                 const float* __restrict__ g,
                                                 const float* __restrict__ b,
                                                 __half* __restrict__ out) {
    ln_body(blockIdx.x * 8 + (threadIdx.x >> 5), threadIdx.x & 31, x, g, b, out);
}

// ---------------------------------------------------------------------------
// Weight transpose body: w[K,N] fp32 tile -> o[N,K] fp16.
// ---------------------------------------------------------------------------
__device__ __forceinline__ void wsplit_body(int blk,
    const float* __restrict__ w0, const float* __restrict__ w1,
    const float* __restrict__ w2, const float* __restrict__ w3,
    __half* __restrict__ o0, __half* __restrict__ o1,
    __half* __restrict__ o2, __half* __restrict__ o3) {
    __shared__ float t[32][33];
    const float* w; __half* o; int K, N, bx, by;
    if (blk < 1728)      { blk -= 0;    w = w0; o = o0; K = 768;  N = 2304; bx = blk % 72; by = blk / 72; }
    else if (blk < 2304) { blk -= 1728; w = w1; o = o1; K = 768;  N = 768;  bx = blk % 24; by = blk / 24; }
    else if (blk < 4608) { blk -= 2304; w = w2; o = o2; K = 768;  N = 3072; bx = blk % 96; by = blk / 96; }
    else                 { blk -= 4608; w = w3; o = o3; K = 3072; N = 768;  bx = blk % 24; by = blk / 24; }
    int n0 = bx * 32, k0 = by * 32;
    int tx = threadIdx.x & 31, ty = threadIdx.x >> 5;
    #pragma unroll
    for (int j = 0; j < 32; j += 8)
        t[ty + j][tx] = w[(size_t)(k0 + ty + j) * N + n0 + tx];
    __syncthreads();
    #pragma unroll
    for (int j = 0; j < 32; j += 8)
        o[(size_t)(n0 + ty + j) * K + k0 + tx] = __float2half_rn(t[tx][ty + j]);
}

// Fused prelude: blocks [0,6912) transpose weights; [6912,7936) do LN1.
__global__ void __launch_bounds__(256) prelude_kernel(
    const float* __restrict__ w0, const float* __restrict__ w1,
    const float* __restrict__ w2, const float* __restrict__ w3,
    __half* __restrict__ o0, __half* __restrict__ o1,
    __half* __restrict__ o2, __half* __restrict__ o3,
    const float* __restrict__ x, const float* __restrict__ ln_g,
    const float* __restrict__ ln_b, __half* __restrict__ h) {
    int blk = blockIdx.x;
    if (blk < 6912) {
        wsplit_body(blk, w0, w1, w2, w3, o0, o1, o2, o3);
    } else {
        ln_body((blk - 6912) * 8 + (threadIdx.x >> 5), threadIdx.x & 31, x, ln_g, ln_b, h);
    }
}

// ---------------------------------------------------------------------------
// fp16 mma.sync GEMM (R14-frozen): C[M,N] = A[M,K] @ B[N,K]^T + bias
// CTA 128x128, BK=64, 8 warps (4 M x 2 N), warp tile 32x64.
// 3-stage cp.async pipeline, rows padded to 144B (conflict-free ldmatrix).
// MODE 1: fp32 +bias+residual;  MODE 2: +bias, GELU -> fp16
// MODE 3: fp16 qkv scatter to per-head q/k/v (q scaled by 0.125*log2e)
// ---------------------------------------------------------------------------
constexpr int GBK = 64;
constexpr int RSTRIDE = 144;                    // 128B payload + 16B pad
constexpr int STAGE_B = 256 * RSTRIDE;          // A(128 rows) + B(128 rows): 36864 B
constexpr int NSTAGE = 3;
constexpr size_t GEMM_SMEM = (size_t)NSTAGE * STAGE_B;  // 110592 B

template <int MODE>
__global__ void __launch_bounds__(256, 2) gemm_mma(
    const __half* __restrict__ A, const __half* __restrict__ B,
    const float* __restrict__ bias, const float* __restrict__ res,
    float* __restrict__ C, __half* __restrict__ Ch,
    __half* __restrict__ Qo, __half* __restrict__ Ko, __half* __restrict__ Vo,
    int Ndim, int Kdim) {
    extern __shared__ __align__(16) char smem[];
    uint32_t sb = smem_u32(smem);
    int tid = threadIdx.x, wid = tid >> 5, lane = tid & 31;
    int wm = wid & 3, wn = wid >> 2;           // warp grid 4 (M) x 2 (N)
    int m0 = blockIdx.y * 128, n0 = blockIdx.x * 128;
    int r = lane >> 2, c2 = (lane & 3) * 2;
    int lrow = lane & 15, lcol = (lane >> 4) * 16;

    float acc[2][8][4];
    #pragma unroll
    for (int mi = 0; mi < 2; mi++)
        #pragma unroll
        for (int ni = 0; ni < 8; ni++)
            #pragma unroll
            for (int q = 0; q < 4; q++) acc[mi][ni][q] = 0.f;

    // 2048 16B chunks per stage (256 rows x 8 chunks), 8 per thread
    auto load_stage = [&](int it, int buf) {
        int k0 = it * GBK;
        #pragma unroll
        for (int i = 0; i < 8; i++) {
            int ch = i * 256 + tid;
            int row = ch >> 3, kc = ch & 7;
            uint32_t dst = sb + buf * STAGE_B + row * RSTRIDE + kc * 16;
            const __half* src = (row < 128 ? A + (size_t)(m0 + row) * Kdim
                                           : B + (size_t)(n0 + row - 128) * Kdim)
                                + k0 + kc * 8;
            CP_ASYNC16(dst, src);
        }
        CP_COMMIT();
    };

    load_stage(0, 0);
    load_stage(1, 1);

    int niter = Kdim / GBK;
    for (int it = 0; it < niter; ++it) {
        int buf = it % NSTAGE;
        if (it + 1 < niter) CP_WAIT(1); else CP_WAIT(0);
        __syncthreads();
        if (it + 2 < niter) load_stage(it + 2, (it + 2) % NSTAGE);

        uint32_t abase = sb + buf * STAGE_B;
        uint32_t bbase = abase + 128 * RSTRIDE;

        #pragma unroll
        for (int ks = 0; ks < 4; ks++) {
            uint32_t ah[2][4];
            #pragma unroll
            for (int mi = 0; mi < 2; mi++) {
                uint32_t addr = abase + (wm * 32 + mi * 16 + lrow) * RSTRIDE + ks * 32 + lcol;
                LDMX4(ah[mi][0], ah[mi][1], ah[mi][2], ah[mi][3], addr);
            }
            #pragma unroll
            for (int nb = 0; nb < 4; nb++) {
                uint32_t b0, b1, b2, b3;
                uint32_t addr = bbase + (wn * 64 + nb * 16 + lrow) * RSTRIDE + ks * 32 + lcol;
                LDMX4(b0, b1, b2, b3, addr);
                #pragma unroll
                for (int mi = 0; mi < 2; mi++) {
                    MMA16816F16(acc[mi][2 * nb],     ah[mi][0], ah[mi][1], ah[mi][2], ah[mi][3], b0, b2);
                    MMA16816F16(acc[mi][2 * nb + 1], ah[mi][0], ah[mi][1], ah[mi][2], ah[mi][3], b1, b3);
                }
            }
        }
    }

    // Epilogue: direct register writeout
    #pragma unroll
    for (int mi = 0; mi < 2; mi++) {
        #pragma unroll
        for (int ni = 0; ni < 8; ni++) {
            int row = m0 + wm * 32 + mi * 16 + r;
            int col = n0 + wn * 64 + ni * 8 + c2;
            float2 bv = *(const float2*)&bias[col];
            #pragma unroll
            for (int hf = 0; hf < 2; hf++) {
                int rr = row + hf * 8;
                float v0 = acc[mi][ni][hf * 2 + 0] + bv.x;
                float v1 = acc[mi][ni][hf * 2 + 1] + bv.y;
                if (MODE == 3) {
                    int which = col / 768;
                    int h = (col % 768) >> 6;
                    int d = col & 63;
                    size_t dst = ((size_t)((rr >> 10) * 12 + h) * 1024 + (rr & 1023)) * 64 + d;
                    __half* base = (which == 0) ? Qo : (which == 1) ? Ko : Vo;
                    float sc = (which == 0) ? 0.1803368823f : 1.0f;  // 0.125*log2(e)
                    *(__half2*)&base[dst] = __floats2half2_rn(v0 * sc, v1 * sc);
                } else {
                    size_t gi = (size_t)rr * Ndim + col;
                    if (MODE == 2) {
                        v0 = 0.5f * v0 * (1.0f + erff(v0 * 0.70710678118f));
                        v1 = 0.5f * v1 * (1.0f + erff(v1 * 0.70710678118f));
                        *(__half2*)&Ch[gi] = __floats2half2_rn(v0, v1);
                    } else {
                        float2 rv = *(const float2*)&res[gi];
                        v0 += rv.x; v1 += rv.y;
                        *(float2*)&C[gi] = make_float2(v0, v1);
                    }
                }
            }
        }
    }
}

// ---------------------------------------------------------------------------
// Tensor-core flash attention (fp16 mma, FA2-style), 64-row Q tiles,
// 128 threads, double-buffered KV via cp.async (R14-exact).
// qt mapped DESCENDING so long CTAs schedule first.
// ---------------------------------------------------------------------------
constexpr int AQS = 72;                         // padded row stride (halves) = 144B
constexpr int ATT_TILE_B = 64 * AQS * 2;        // 9216 B
constexpr size_t ATT_SMEM = 5 * ATT_TILE_B;     // Q + 2*K + 2*V = 46080 B

__global__ void __launch_bounds__(128) attn_kernel() {
    extern __shared__ __align__(16) char smem[];
    uint32_t sb = smem_u32(smem);
    uint32_t Qb = sb;
    uint32_t Kb[2] = {sb + ATT_TILE_B, sb + 2 * ATT_TILE_B};
    uint32_t Vb[2] = {sb + 3 * ATT_TILE_B, sb + 4 * ATT_TILE_B};

    int qt = (int)(gridDim.x - 1 - blockIdx.x);  // long CTAs first
    int nh = blockIdx.y;                        // n*12 + h
    size_t hbase = (size_t)nh * 1024 * 64;      // head base in g_q/g_k/g_v
    int n = nh / 12, h = nh % 12;
    int tid = threadIdx.x, wid = tid >> 5, lane = tid & 31;
    int r = lane >> 2, c2 = (lane & 3) * 2;
    int lrow = lane & 15, lcol = (lane >> 4) * 16;  // 16B units

    auto load_tile = [&](const __half* g, int t0, uint32_t dstb) {
        #pragma unroll
        for (int i = 0; i < 4; i++) {
            int ch = i * 128 + tid;
            int row = ch >> 3, kc = ch & 7;
            CP_ASYNC16(dstb + row * (AQS * 2) + kc * 16,
                       g + hbase + (size_t)(t0 + row) * 64 + kc * 8);
        }
        CP_COMMIT();
    };

    load_tile(g_q, qt * 64, Qb);
    load_tile(g_k, 0, Kb[0]);
    load_tile(g_v, 0, Vb[0]);
    CP_WAIT(0);
    __syncthreads();

    uint32_t qf[4][4];
    #pragma unroll
    for (int kb = 0; kb < 4; kb++) {
        uint32_t addr = Qb + (wid * 16 + lrow) * (AQS * 2) + kb * 32 + lcol;
        LDMX4(qf[kb][0], qf[kb][1], qf[kb][2], qf[kb][3], addr);
    }

    float m0v = -1e30f, m1v = -1e30f, l0 = 0.f, l1 = 0.f;
    float o[8][4];
    #pragma unroll
    for (int db = 0; db < 8; db++)
        #pragma unroll
        for (int q = 0; q < 4; q++) o[db][q] = 0.f;

    for (int t = 0; t <= qt; ++t) {
        int buf = t & 1;
        if (t < qt) {
            load_tile(g_k, (t + 1) * 64, Kb[buf ^ 1]);
            load_tile(g_v, (t + 1) * 64, Vb[buf ^ 1]);
        }

        // S = Q @ K^T  (16 x 64 per warp)  — values in log2 domain
        float s[8][4];
        #pragma unroll
        for (int nb = 0; nb < 8; nb++)
            #pragma unroll
            for (int q = 0; q < 4; q++) s[nb][q] = 0.f;
        #pragma unroll
        for (int kb = 0; kb < 4; kb++) {
            #pragma unroll
            for (int nb16 = 0; nb16 < 4; nb16++) {
                uint32_t b0, b1, b2, b3;
                uint32_t addr = Kb[buf] + (nb16 * 16 + lrow) * (AQS * 2) + kb * 32 + lcol;
                LDMX4(b0, b1, b2, b3, addr);
                MMA16816F16(s[nb16 * 2],     qf[kb][0], qf[kb][1], qf[kb][2], qf[kb][3], b0, b2);
                MMA16816F16(s[nb16 * 2 + 1], qf[kb][0], qf[kb][1], qf[kb][2], qf[kb][3], b1, b3);
            }
        }

        // Causal mask on diagonal tile
        if (t == qt) {
            int row0 = qt * 64 + wid * 16 + r;
            #pragma unroll
            for (int nb = 0; nb < 8; nb++) {
                int col = t * 64 + nb * 8 + c2;
                if (col > row0)     s[nb][0] = -1e30f;
                if (col + 1 > row0) s[nb][1] = -1e30f;
                if (col > row0 + 8)     s[nb][2] = -1e30f;
                if (col + 1 > row0 + 8) s[nb][3] = -1e30f;
            }
        }

        // Online softmax (rows r and r+8 of this warp's 16), exp2 domain
        float mx0 = -1e30f, mx1 = -1e30f;
        #pragma unroll
        for (int nb = 0; nb < 8; nb++) {
            mx0 = fmaxf(mx0, fmaxf(s[nb][0], s[nb][1]));
            mx1 = fmaxf(mx1, fmaxf(s[nb][2], s[nb][3]));
        }
        mx0 = fmaxf(mx0, __shfl_xor_sync(0xffffffffu, mx0, 1));
        mx0 = fmaxf(mx0, __shfl_xor_sync(0xffffffffu, mx0, 2));
        mx1 = fmaxf(mx1, __shfl_xor_sync(0xffffffffu, mx1, 1));
        mx1 = fmaxf(mx1, __shfl_xor_sync(0xffffffffu, mx1, 2));

        float nm0 = fmaxf(m0v, mx0), nm1 = fmaxf(m1v, mx1);
        float f0 = exp2f(m0v - nm0), f1 = exp2f(m1v - nm1);
        float ls0 = 0.f, ls1 = 0.f;
        #pragma unroll
        for (int nb = 0; nb < 8; nb++) {
            s[nb][0] = exp2f(s[nb][0] - nm0); ls0 += s[nb][0];
            s[nb][1] = exp2f(s[nb][1] - nm0); ls0 += s[nb][1];
            s[nb][2] = exp2f(s[nb][2] - nm1); ls1 += s[nb][2];
            s[nb][3] = exp2f(s[nb][3] - nm1); ls1 += s[nb][3];
        }
        l0 = l0 * f0 + ls0;
        l1 = l1 * f1 + ls1;
        m0v = nm0; m1v = nm1;
        #pragma unroll
        for (int db = 0; db < 8; db++) {
            o[db][0] *= f0; o[db][1] *= f0;
            o[db][2] *= f1; o[db][3] *= f1;
        }

        // O += P @ V  (P fp16 from registers)
        #pragma unroll
        for (int kb2 = 0; kb2 < 4; kb2++) {
            uint32_t a0 = packh2(s[2 * kb2][0],     s[2 * kb2][1]);
            uint32_t a1 = packh2(s[2 * kb2][2],     s[2 * kb2][3]);
            uint32_t a2 = packh2(s[2 * kb2 + 1][0], s[2 * kb2 + 1][1]);
            uint32_t a3 = packh2(s[2 * kb2 + 1][2], s[2 * kb2 + 1][3]);
            #pragma unroll
            for (int db2 = 0; db2 < 4; db2++) {
                uint32_t v0, v1, v2, v3;
                uint32_t addr = Vb[buf] + (kb2 * 16 + lrow) * (AQS * 2) + db2 * 32 + lcol;
                LDMX4T(v0, v1, v2, v3, addr);
                MMA16816F16(o[db2 * 2],     a0, a1, a2, a3, v0, v1);
                MMA16816F16(o[db2 * 2 + 1], a0, a1, a2, a3, v2, v3);
            }
        }

        if (t < qt) {
            CP_WAIT(0);
            __syncthreads();
        }
    }

    l0 += __shfl_xor_sync(0xffffffffu, l0, 1);
    l0 += __shfl_xor_sync(0xffffffffu, l0, 2);
    l1 += __shfl_xor_sync(0xffffffffu, l1, 1);
    l1 += __shfl_xor_sync(0xffffffffu, l1, 2);
    float inv0 = 1.f / l0, inv1 = 1.f / l1;

    int row0 = n * 1024 + qt * 64 + wid * 16 + r;
    int colb = h * 64;
    #pragma unroll
    for (int db = 0; db < 8; db++) {
        size_t gi0 = (size_t)row0 * 768 + colb + db * 8 + c2;
        size_t gi1 = (size_t)(row0 + 8) * 768 + colb + db * 8 + c2;
        *(__half2*)&g_attn[gi0] = __floats2half2_rn(o[db][0] * inv0, o[db][1] * inv0);
        *(__half2*)&g_attn[gi1] = __floats2half2_rn(o[db][2] * inv1, o[db][3] * inv1);
    }
}

// ---------------------------------------------------------------------------
extern "C" void kernel_launch(void* const* d_in, const int* in_sizes, int n_in,
                              void* d_out, int out_size) {
    const float* x      = (const float*)d_in[0];
    const float* ln1_g  = (const float*)d_in[1];
    const float* ln1_b  = (const float*)d_in[2];
    const float* ln2_g  = (const float*)d_in[3];
    const float* ln2_b  = (const float*)d_in[4];
    const float* w_attn = (const float*)d_in[5];
    const float* b_attn = (const float*)d_in[6];
    const float* w_proj = (const float*)d_in[7];
    const float* b_proj = (const float*)d_in[8];
    const float* w_fc   = (const float*)d_in[9];
    const float* b_fc   = (const float*)d_in[10];
    const float* w_fc2  = (const float*)d_in[11];
    const float* b_fc2  = (const float*)d_in[12];
    float* out = (float*)d_out;

    float* p_x1;
    __half *p_h, *p_attn, *p_ff, *p_q, *p_k, *p_v;
    __half *p_wq, *p_wp, *p_wf, *p_w2;
    cudaGetSymbolAddress((void**)&p_x1, g_x1);
    cudaGetSymbolAddress((void**)&p_h, g_h);
    cudaGetSymbolAddress((void**)&p_attn, g_attn);
    cudaGetSymbolAddress((void**)&p_ff, g_ff);
    cudaGetSymbolAddress((void**)&p_q, g_q);
    cudaGetSymbolAddress((void**)&p_k, g_k);
    cudaGetSymbolAddress((void**)&p_v, g_v);
    cudaGetSymbolAddress((void**)&p_wq, g_wqkv);
    cudaGetSymbolAddress((void**)&p_wp, g_wproj);
    cudaGetSymbolAddress((void**)&p_wf, g_wfc);
    cudaGetSymbolAddress((void**)&p_w2, g_wfc2);

    cudaFuncSetAttribute(gemm_mma<1>, cudaFuncAttributeMaxDynamicSharedMemorySize, (int)GEMM_SMEM);
    cudaFuncSetAttribute(gemm_mma<2>, cudaFuncAttributeMaxDynamicSharedMemorySize, (int)GEMM_SMEM);
    cudaFuncSetAttribute(gemm_mma<3>, cudaFuncAttributeMaxDynamicSharedMemorySize, (int)GEMM_SMEM);
    cudaFuncSetAttribute(attn_kernel, cudaFuncAttributeMaxDynamicSharedMemorySize, (int)ATT_SMEM);

    // 0+1. fused prelude: weight transposes + LN1
    prelude_kernel<<<7936, 256>>>(w_attn, w_proj, w_fc, w_fc2,
                                  p_wq, p_wp, p_wf, p_w2,
                                  x, ln1_g, ln1_b, p_h);
    // 2. qkv GEMM -> per-head q/k/v fp16 (q scaled by 0.125*log2e)
    gemm_mma<3><<<dim3(18, 64), 256, GEMM_SMEM>>>(p_h, p_wq, b_attn, nullptr,
        nullptr, nullptr, p_q, p_k, p_v, E3, E);
    // 3. tensor-core causal flash attention -> attn (fp16 [rows, E])
    attn_kernel<<<dim3(16, 96), 128, ATT_SMEM>>>();
    // 4. x1 = x + attn @ w_proj + b_proj
    gemm_mma<1><<<dim3(6, 64), 256, GEMM_SMEM>>>(p_attn, p_wp, b_proj, x,
        p_x1, nullptr, nullptr, nullptr, nullptr, E, E);
    // 5. LN2 -> h (fp16)
    ln_kernel<<<1024, 256>>>(p_x1, ln2_g, ln2_b, p_h);
    // 6. ff = gelu(h @ w_fc + b_fc) -> fp16
    gemm_mma<2><<<dim3(24, 64), 256, GEMM_SMEM>>>(p_h, p_wf, b_fc, nullptr,
        nullptr, p_ff, nullptr, nullptr, nullptr, FF, E);
    // 7. out = x1 + ff @ w_fc2 + b_fc2
    gemm_mma<1><<<dim3(6, 64), 256, GEMM_SMEM>>>(p_ff, p_w2, b_fc2, p_x1,
        out, nullptr, nullptr, nullptr, nullptr, E, FF);
}